// round 4
// baseline (speedup 1.0000x reference)
#include <cuda_runtime.h>
#include <math.h>

#define DIMD 1024
#define NTOK 1024
#define BSZ 8
#define NH 16
#define HD 64
#define MTOT (BSZ * NTOK)   // 8192
#define ATT_SCALE 0.125f    // 64^-0.5
#define SOFT_CAP 50.0f

// ---------------- scratch (device globals; no allocation allowed) ----------
__device__ float g_q[MTOT * DIMD];
__device__ float g_k[MTOT * DIMD];
__device__ float g_v[MTOT * DIMD];
__device__ float g_ctx[MTOT * DIMD];
__device__ int   g_maskmode;   // 1 = uint8 layout, 4 = int32/float32 word layout

// ---------------------------------------------------------------------------
// Detect mask element width using the guaranteed-True diagonal.
// uint8 layout: byte[i*1025] == 1 for all i.
// int32/float32 layout: byte probe hits mid/high bytes of 0/1 words -> fails.
// ---------------------------------------------------------------------------
__global__ void detect_maskmode(const unsigned char* __restrict__ m)
{
    bool u8ok = true;
    for (int i = 0; i < 64; i++)
        if (m[(size_t)i * 1025] == 0) { u8ok = false; break; }
    g_maskmode = u8ok ? 1 : 4;
}

// ---------------------------------------------------------------------------
// SGEMM: C[M,1024] = A[M,1024] @ B[1024,1024]^T    (both K-major / NT)
// 128x128x8 tiles, 256 threads, 8x8 micro-tile, transposed smem staging.
// ---------------------------------------------------------------------------
__global__ __launch_bounds__(256)
void sgemm_nt(const float* __restrict__ A, const float* __restrict__ B,
              float* __restrict__ C)
{
    __shared__ float As[8][132];
    __shared__ float Bs[8][132];

    const int tid = threadIdx.x;
    const int tx = tid & 15;
    const int ty = tid >> 4;
    const int m0 = blockIdx.y * 128;
    const int n0 = blockIdx.x * 128;

    const int lrow = tid >> 1;          // 0..127
    const int lc4  = (tid & 1) * 4;     // 0 or 4
    const float* Ap = A + (size_t)(m0 + lrow) * DIMD + lc4;
    const float* Bp = B + (size_t)(n0 + lrow) * DIMD + lc4;

    float acc[8][8];
    #pragma unroll
    for (int i = 0; i < 8; i++)
        #pragma unroll
        for (int j = 0; j < 8; j++) acc[i][j] = 0.f;

    for (int k0 = 0; k0 < DIMD; k0 += 8) {
        float4 av = *(const float4*)(Ap + k0);
        float4 bv = *(const float4*)(Bp + k0);
        __syncthreads();
        As[lc4 + 0][lrow] = av.x; As[lc4 + 1][lrow] = av.y;
        As[lc4 + 2][lrow] = av.z; As[lc4 + 3][lrow] = av.w;
        Bs[lc4 + 0][lrow] = bv.x; Bs[lc4 + 1][lrow] = bv.y;
        Bs[lc4 + 2][lrow] = bv.z; Bs[lc4 + 3][lrow] = bv.w;
        __syncthreads();
        #pragma unroll
        for (int kk = 0; kk < 8; kk++) {
            float4 a0 = *(const float4*)&As[kk][ty * 8];
            float4 a1 = *(const float4*)&As[kk][ty * 8 + 4];
            float4 b0 = *(const float4*)&Bs[kk][tx * 8];
            float4 b1 = *(const float4*)&Bs[kk][tx * 8 + 4];
            float a[8] = {a0.x, a0.y, a0.z, a0.w, a1.x, a1.y, a1.z, a1.w};
            float b[8] = {b0.x, b0.y, b0.z, b0.w, b1.x, b1.y, b1.z, b1.w};
            #pragma unroll
            for (int i = 0; i < 8; i++)
                #pragma unroll
                for (int j = 0; j < 8; j++) acc[i][j] += a[i] * b[j];
        }
    }

    #pragma unroll
    for (int i = 0; i < 8; i++) {
        float* Cp = C + (size_t)(m0 + ty * 8 + i) * DIMD + n0 + tx * 8;
        *(float4*)(Cp)     = make_float4(acc[i][0], acc[i][1], acc[i][2], acc[i][3]);
        *(float4*)(Cp + 4) = make_float4(acc[i][4], acc[i][5], acc[i][6], acc[i][7]);
    }
}

// ---------------------------------------------------------------------------
// RMSNorm (per head) + gathered 2D RoPE for q and k, in place.
// ---------------------------------------------------------------------------
__global__ __launch_bounds__(128)
void normrope(float* __restrict__ q, float* __restrict__ k,
              const float* __restrict__ qg, const float* __restrict__ kg,
              const float* __restrict__ cosT, const float* __restrict__ sinT,
              const int* __restrict__ ridx)
{
    const int token = blockIdx.x;            // b*N + n
    const int n = token & (NTOK - 1);
    const int lane = threadIdx.x & 31;
    const int w = threadIdx.x >> 5;

    const int rid = ridx[n];
    const bool dorope = (rid >= 0);
    float c0 = 1.f, c1 = 1.f, s0 = 0.f, s1 = 0.f;
    if (dorope) {
        c0 = cosT[rid * HD + lane];
        c1 = cosT[rid * HD + lane + 32];
        s0 = sinT[rid * HD + lane];
        s1 = sinT[rid * HD + lane + 32];
    }
    const float qg0 = qg[lane], qg1 = qg[lane + 32];
    const float kg0 = kg[lane], kg1 = kg[lane + 32];

    #pragma unroll
    for (int hh = 0; hh < 4; hh++) {
        const int h = w * 4 + hh;
        const size_t base = (size_t)token * DIMD + h * HD;

        {
            float x0 = q[base + lane];
            float x1 = q[base + lane + 32];
            float ss = x0 * x0 + x1 * x1;
            #pragma unroll
            for (int off = 16; off >= 1; off >>= 1)
                ss += __shfl_xor_sync(0xffffffffu, ss, off);
            float r = rsqrtf(ss * (1.f / 64.f) + 1e-6f);
            float y0 = x0 * r * qg0;
            float y1 = x1 * r * qg1;
            q[base + lane]      = dorope ? (y0 * c0 - y1 * s0) : y0;
            q[base + lane + 32] = dorope ? (y1 * c1 + y0 * s1) : y1;
        }
        {
            float x0 = k[base + lane];
            float x1 = k[base + lane + 32];
            float ss = x0 * x0 + x1 * x1;
            #pragma unroll
            for (int off = 16; off >= 1; off >>= 1)
                ss += __shfl_xor_sync(0xffffffffu, ss, off);
            float r = rsqrtf(ss * (1.f / 64.f) + 1e-6f);
            float y0 = x0 * r * kg0;
            float y1 = x1 * r * kg1;
            k[base + lane]      = dorope ? (y0 * c0 - y1 * s0) : y0;
            k[base + lane + 32] = dorope ? (y1 * c1 + y0 * s1) : y1;
        }
    }
}

// ---------------------------------------------------------------------------
// Attention: per (b, h, 128-query tile). 16 key tiles of 64.
// Soft cap bounds scores to (-50,50): exp without running max is fp32-safe.
// ---------------------------------------------------------------------------
#define QT_STRIDE 132
#define KV_STRIDE 68
#define SM_QT 0
#define SM_KT (64 * QT_STRIDE)
#define SM_VS (SM_KT + 64 * KV_STRIDE)
#define SM_PT (SM_VS + 64 * KV_STRIDE)
#define SM_RS (SM_PT + 64 * QT_STRIDE)
#define ATT_SMEM_FLOATS (SM_RS + 128)
#define ATT_SMEM_BYTES (ATT_SMEM_FLOATS * 4)

__global__ __launch_bounds__(256)
void attn_kernel(const float* __restrict__ q, const float* __restrict__ k,
                 const float* __restrict__ v,
                 const unsigned char* __restrict__ mask,
                 float* __restrict__ ctx)
{
    extern __shared__ float sm[];
    float (*Qt)[QT_STRIDE] = (float(*)[QT_STRIDE])(sm + SM_QT);
    float (*Kt)[KV_STRIDE] = (float(*)[KV_STRIDE])(sm + SM_KT);
    float (*Vs)[KV_STRIDE] = (float(*)[KV_STRIDE])(sm + SM_VS);
    float (*Pt)[QT_STRIDE] = (float(*)[QT_STRIDE])(sm + SM_PT);
    float* rowsum = sm + SM_RS;

    const int tid = threadIdx.x;
    const int tx = tid & 15;
    const int ty = tid >> 4;
    const int m0 = blockIdx.x * 128;
    const int h = blockIdx.y;
    const int b = blockIdx.z;
    const int mmode = g_maskmode;        // uniform across grid

    const size_t head_off = (size_t)h * HD;
    const size_t brow = (size_t)b * NTOK;

    #pragma unroll
    for (int u = 0; u < 8; u++) {
        int f = tid + 256 * u;
        int row = f >> 4;
        int c4 = (f & 15) * 4;
        float4 val = *(const float4*)(q + (brow + m0 + row) * DIMD + head_off + c4);
        Qt[c4 + 0][row] = val.x; Qt[c4 + 1][row] = val.y;
        Qt[c4 + 2][row] = val.z; Qt[c4 + 3][row] = val.w;
    }
    if (tid < 128) rowsum[tid] = 0.f;

    float acc[8][4];
    #pragma unroll
    for (int i = 0; i < 8; i++)
        #pragma unroll
        for (int j = 0; j < 4; j++) acc[i][j] = 0.f;

    for (int k0 = 0; k0 < NTOK; k0 += 64) {
        __syncthreads();
        #pragma unroll
        for (int u = 0; u < 4; u++) {
            int f = tid + 256 * u;
            int row = f >> 4;
            int c4 = (f & 15) * 4;
            float4 kv = *(const float4*)(k + (brow + k0 + row) * DIMD + head_off + c4);
            Kt[c4 + 0][row] = kv.x; Kt[c4 + 1][row] = kv.y;
            Kt[c4 + 2][row] = kv.z; Kt[c4 + 3][row] = kv.w;
            float4 vv = *(const float4*)(v + (brow + k0 + row) * DIMD + head_off + c4);
            *(float4*)&Vs[row][c4] = vv;
        }
        __syncthreads();

        // ---- phase A: S = Q K^T ----
        float s[8][4];
        #pragma unroll
        for (int i = 0; i < 8; i++)
            #pragma unroll
            for (int j = 0; j < 4; j++) s[i][j] = 0.f;

        #pragma unroll 4
        for (int kk = 0; kk < 64; kk++) {
            float4 a0 = *(const float4*)&Qt[kk][ty * 8];
            float4 a1 = *(const float4*)&Qt[kk][ty * 8 + 4];
            float4 b0 = *(const float4*)&Kt[kk][tx * 4];
            float a[8] = {a0.x, a0.y, a0.z, a0.w, a1.x, a1.y, a1.z, a1.w};
            float bb[4] = {b0.x, b0.y, b0.z, b0.w};
            #pragma unroll
            for (int i = 0; i < 8; i++)
                #pragma unroll
                for (int j = 0; j < 4; j++) s[i][j] += a[i] * bb[j];
        }

        // ---- soft cap + mask + exp ----
        float rs[8];
        #pragma unroll
        for (int i = 0; i < 8; i++) {
            const int qrow = m0 + ty * 8 + i;
            int mm[4];
            if (mmode == 1) {
                uchar4 mk = *(const uchar4*)(mask + (size_t)qrow * NTOK + k0 + tx * 4);
                mm[0] = mk.x; mm[1] = mk.y; mm[2] = mk.z; mm[3] = mk.w;
            } else {
                const int* m32 = (const int*)mask;
                int4 mk = *(const int4*)(m32 + (size_t)qrow * NTOK + k0 + tx * 4);
                mm[0] = mk.x; mm[1] = mk.y; mm[2] = mk.z; mm[3] = mk.w;
            }
            rs[i] = 0.f;
            #pragma unroll
            for (int j = 0; j < 4; j++) {
                float sc = s[i][j] * ATT_SCALE;
                sc = SOFT_CAP * tanhf(sc * (1.f / SOFT_CAP));
                float p = mm[j] ? __expf(sc) : 0.f;
                s[i][j] = p;
                rs[i] += p;
            }
        }
        #pragma unroll
        for (int i = 0; i < 8; i++) {
            rs[i] += __shfl_xor_sync(0xffffffffu, rs[i], 8);
            rs[i] += __shfl_xor_sync(0xffffffffu, rs[i], 4);
            rs[i] += __shfl_xor_sync(0xffffffffu, rs[i], 2);
            rs[i] += __shfl_xor_sync(0xffffffffu, rs[i], 1);
        }
        if (tx == 0) {
            #pragma unroll
            for (int i = 0; i < 8; i++) rowsum[ty * 8 + i] += rs[i];
        }

        #pragma unroll
        for (int j = 0; j < 4; j++) {
            *(float4*)&Pt[tx * 4 + j][ty * 8] =
                make_float4(s[0][j], s[1][j], s[2][j], s[3][j]);
            *(float4*)&Pt[tx * 4 + j][ty * 8 + 4] =
                make_float4(s[4][j], s[5][j], s[6][j], s[7][j]);
        }
        __syncthreads();

        // ---- phase B: acc += P V ----
        #pragma unroll 4
        for (int kk = 0; kk < 64; kk++) {
            float4 a0 = *(const float4*)&Pt[kk][ty * 8];
            float4 a1 = *(const float4*)&Pt[kk][ty * 8 + 4];
            float4 b0 = *(const float4*)&Vs[kk][tx * 4];
            float a[8] = {a0.x, a0.y, a0.z, a0.w, a1.x, a1.y, a1.z, a1.w};
            float bb[4] = {b0.x, b0.y, b0.z, b0.w};
            #pragma unroll
            for (int i = 0; i < 8; i++)
                #pragma unroll
                for (int j = 0; j < 4; j++) acc[i][j] += a[i] * bb[j];
        }
    }
    __syncthreads();

    #pragma unroll
    for (int i = 0; i < 8; i++) {
        float inv = 1.f / rowsum[ty * 8 + i];
        float4 o = make_float4(acc[i][0] * inv, acc[i][1] * inv,
                               acc[i][2] * inv, acc[i][3] * inv);
        *(float4*)(ctx + (brow + m0 + ty * 8 + i) * DIMD + head_off + tx * 4) = o;
    }
}

// ---------------------------------------------------------------------------
extern "C" void kernel_launch(void* const* d_in, const int* in_sizes, int n_in,
                              void* d_out, int out_size)
{
    (void)in_sizes; (void)n_in; (void)out_size;
    const float* x   = (const float*)d_in[0];
    const float* Wq  = (const float*)d_in[1];
    const float* Wk  = (const float*)d_in[2];
    const float* Wv  = (const float*)d_in[3];
    const float* Wo  = (const float*)d_in[4];
    const float* qg  = (const float*)d_in[5];
    const float* kg  = (const float*)d_in[6];
    const float* cosT = (const float*)d_in[7];
    const float* sinT = (const float*)d_in[8];
    const int*   ridx = (const int*)d_in[9];
    const unsigned char* mask = (const unsigned char*)d_in[10];
    float* out = (float*)d_out;

    float *qp, *kp, *vp, *cp;
    cudaGetSymbolAddress((void**)&qp, g_q);
    cudaGetSymbolAddress((void**)&kp, g_k);
    cudaGetSymbolAddress((void**)&vp, g_v);
    cudaGetSymbolAddress((void**)&cp, g_ctx);

    cudaFuncSetAttribute(attn_kernel,
                         cudaFuncAttributeMaxDynamicSharedMemorySize,
                         ATT_SMEM_BYTES);

    detect_maskmode<<<1, 1>>>(mask);

    dim3 gemm_grid(DIMD / 128, MTOT / 128);   // (8, 64)
    sgemm_nt<<<gemm_grid, 256>>>(x, Wq, qp);
    sgemm_nt<<<gemm_grid, 256>>>(x, Wk, kp);
    sgemm_nt<<<gemm_grid, 256>>>(x, Wv, vp);

    normrope<<<MTOT, 128>>>(qp, kp, qg, kg, cosT, sinT, ridx);

    dim3 att_grid(NTOK / 128, NH, BSZ);       // (8, 16, 8)
    attn_kernel<<<att_grid, 256, ATT_SMEM_BYTES>>>(qp, kp, vp, mask, cp);

    sgemm_nt<<<gemm_grid, 256>>>(cp, Wo, out);
}

// round 5
// speedup vs baseline: 1.5540x; 1.5540x over previous
#include <cuda_runtime.h>
#include <cuda_bf16.h>
#include <math.h>
#include <stdint.h>

#define DIMD 1024
#define NTOK 1024
#define BSZ 8
#define NH 16
#define HD 64
#define MTOT (BSZ * NTOK)   // 8192
#define ATT_SCALE 0.125f    // 64^-0.5
#define SOFT_CAP 50.0f

// ---------------- scratch (device globals; no allocation allowed) ----------
__device__ float g_q[MTOT * DIMD];
__device__ float g_k[MTOT * DIMD];
__device__ float g_v[MTOT * DIMD];
__device__ float g_ctx[MTOT * DIMD];
__device__ int   g_maskmode;   // 1 = uint8 layout, 4 = int32/float32 word layout

// ---------------------------------------------------------------------------
// Detect mask element width using the guaranteed-True diagonal.
// ---------------------------------------------------------------------------
__global__ void detect_maskmode(const unsigned char* __restrict__ m)
{
    bool u8ok = true;
    for (int i = 0; i < 64; i++)
        if (m[(size_t)i * 1025] == 0) { u8ok = false; break; }
    g_maskmode = u8ok ? 1 : 4;
}

// ---------------------------------------------------------------------------
// Tensor-core GEMM (split-bf16): C[M,1024] = A[M,1024] @ B[1024,1024]^T (NT)
// a = a_hi + a_lo (bf16 each); C = Ah*Bh + Ah*Bl + Al*Bh  (lo*lo dropped).
// 128x128 tile, K-step 32, 8 warps (4m x 2n), warp tile 32x64.
// smem tiles padded to stride 40 bf16 (80B rows) -> conflict-free ldmatrix.
// ---------------------------------------------------------------------------
#define TCS 40   // smem row stride in bf16 elements

__device__ __forceinline__ void ldsm_x4(uint32_t* r, uint32_t addr)
{
    asm volatile("ldmatrix.sync.aligned.m8n8.x4.shared.b16 {%0,%1,%2,%3}, [%4];\n"
                 : "=r"(r[0]), "=r"(r[1]), "=r"(r[2]), "=r"(r[3]) : "r"(addr));
}

__device__ __forceinline__ void mma16816(float* c, const uint32_t* a, const uint32_t* b)
{
    asm volatile("mma.sync.aligned.m16n8k16.row.col.f32.bf16.bf16.f32 "
                 "{%0,%1,%2,%3}, {%4,%5,%6,%7}, {%8,%9}, {%0,%1,%2,%3};\n"
                 : "+f"(c[0]), "+f"(c[1]), "+f"(c[2]), "+f"(c[3])
                 : "r"(a[0]), "r"(a[1]), "r"(a[2]), "r"(a[3]),
                   "r"(b[0]), "r"(b[1]));
}

__device__ __forceinline__ void split_store(__nv_bfloat16* hi_base, __nv_bfloat16* lo_base,
                                            int off, float4 v)
{
    __nv_bfloat16 h0 = __float2bfloat16(v.x);
    __nv_bfloat16 h1 = __float2bfloat16(v.y);
    __nv_bfloat16 h2 = __float2bfloat16(v.z);
    __nv_bfloat16 h3 = __float2bfloat16(v.w);
    __nv_bfloat16 l0 = __float2bfloat16(v.x - __bfloat162float(h0));
    __nv_bfloat16 l1 = __float2bfloat16(v.y - __bfloat162float(h1));
    __nv_bfloat16 l2 = __float2bfloat16(v.z - __bfloat162float(h2));
    __nv_bfloat16 l3 = __float2bfloat16(v.w - __bfloat162float(h3));
    *(__nv_bfloat162*)(hi_base + off)     = __nv_bfloat162(h0, h1);
    *(__nv_bfloat162*)(hi_base + off + 2) = __nv_bfloat162(h2, h3);
    *(__nv_bfloat162*)(lo_base + off)     = __nv_bfloat162(l0, l1);
    *(__nv_bfloat162*)(lo_base + off + 2) = __nv_bfloat162(l2, l3);
}

__global__ __launch_bounds__(256)
void tc_gemm_nt(const float* __restrict__ A, const float* __restrict__ B,
                float* __restrict__ C)
{
    __shared__ __align__(16) __nv_bfloat16 Ah[128 * TCS];
    __shared__ __align__(16) __nv_bfloat16 Al[128 * TCS];
    __shared__ __align__(16) __nv_bfloat16 Bh[128 * TCS];
    __shared__ __align__(16) __nv_bfloat16 Bl[128 * TCS];

    const int tid = threadIdx.x;
    const int lane = tid & 31;
    const int wid = tid >> 5;
    const int wm = wid & 3;          // 4 m-blocks of 32
    const int wn = wid >> 2;         // 2 n-blocks of 64
    const int m0 = blockIdx.y * 128;
    const int n0 = blockIdx.x * 128;

    // ---- per-thread gmem load slots: 4 float4 for A, 4 for B per K-slab ----
    int lrow[4], lc4[4], soff[4];
    #pragma unroll
    for (int u = 0; u < 4; u++) {
        int f = tid + 256 * u;       // 0..1023 float4 slots (128 rows x 8)
        lrow[u] = f >> 3;
        lc4[u]  = (f & 7) * 4;
        soff[u] = lrow[u] * TCS + lc4[u];
    }

    // ---- ldmatrix lane-address components ----
    const uint32_t Ah_b = (uint32_t)__cvta_generic_to_shared(Ah);
    const uint32_t Al_b = (uint32_t)__cvta_generic_to_shared(Al);
    const uint32_t Bh_b = (uint32_t)__cvta_generic_to_shared(Bh);
    const uint32_t Bl_b = (uint32_t)__cvta_generic_to_shared(Bl);

    // A frags: lanes 0-7 rows m+0..7 k0 / 8-15 rows m+8..15 k0 / 16-23 k+8 / 24-31 k+8
    const int a_row = wm * 32 + (lane & 15);
    const int a_kad = (lane & 16) ? 8 : 0;
    const uint32_t a_off0 = (uint32_t)(a_row * TCS + a_kad) * 2;
    // B frags (x4 = two n-frags): lanes 0-7 n+0..7 k0 / 8-15 n+0..7 k+8 /
    //                             16-23 n+8..15 k0 / 24-31 n+8..15 k+8
    const int b_row = wn * 64 + (lane & 7) + ((lane & 16) ? 8 : 0);
    const int b_kad = (lane & 8) ? 8 : 0;
    const uint32_t b_off0 = (uint32_t)(b_row * TCS + b_kad) * 2;

    float acc[2][8][4];
    #pragma unroll
    for (int mi = 0; mi < 2; mi++)
        #pragma unroll
        for (int nj = 0; nj < 8; nj++)
            #pragma unroll
            for (int c = 0; c < 4; c++) acc[mi][nj][c] = 0.f;

    float4 av[4], bv[4];
    #pragma unroll
    for (int u = 0; u < 4; u++) {
        av[u] = *(const float4*)(A + (size_t)(m0 + lrow[u]) * DIMD + lc4[u]);
        bv[u] = *(const float4*)(B + (size_t)(n0 + lrow[u]) * DIMD + lc4[u]);
    }

    for (int k0 = 0; k0 < DIMD; k0 += 32) {
        __syncthreads();   // previous compute done reading smem
        #pragma unroll
        for (int u = 0; u < 4; u++) {
            split_store(Ah, Al, soff[u], av[u]);
            split_store(Bh, Bl, soff[u], bv[u]);
        }
        __syncthreads();

        if (k0 + 32 < DIMD) {
            #pragma unroll
            for (int u = 0; u < 4; u++) {
                av[u] = *(const float4*)(A + (size_t)(m0 + lrow[u]) * DIMD + k0 + 32 + lc4[u]);
                bv[u] = *(const float4*)(B + (size_t)(n0 + lrow[u]) * DIMD + k0 + 32 + lc4[u]);
            }
        }

        #pragma unroll
        for (int kk = 0; kk < 32; kk += 16) {
            const uint32_t akk = a_off0 + kk * 2;
            const uint32_t bkk = b_off0 + kk * 2;

            uint32_t ah[2][4], al[2][4], bf[4][4];
            ldsm_x4(ah[0], Ah_b + akk);
            ldsm_x4(ah[1], Ah_b + akk + 16 * TCS * 2);
            ldsm_x4(al[0], Al_b + akk);
            ldsm_x4(al[1], Al_b + akk + 16 * TCS * 2);
            #pragma unroll
            for (int nq = 0; nq < 4; nq++)
                ldsm_x4(bf[nq], Bh_b + bkk + nq * 16 * TCS * 2);

            // Ah*Bh and Al*Bh
            #pragma unroll
            for (int mi = 0; mi < 2; mi++)
                #pragma unroll
                for (int nj = 0; nj < 8; nj++)
                    mma16816(acc[mi][nj], ah[mi], &bf[nj >> 1][(nj & 1) * 2]);
            #pragma unroll
            for (int mi = 0; mi < 2; mi++)
                #pragma unroll
                for (int nj = 0; nj < 8; nj++)
                    mma16816(acc[mi][nj], al[mi], &bf[nj >> 1][(nj & 1) * 2]);

            // reload B-lo into same regs, Ah*Bl
            #pragma unroll
            for (int nq = 0; nq < 4; nq++)
                ldsm_x4(bf[nq], Bl_b + bkk + nq * 16 * TCS * 2);
            #pragma unroll
            for (int mi = 0; mi < 2; mi++)
                #pragma unroll
                for (int nj = 0; nj < 8; nj++)
                    mma16816(acc[mi][nj], ah[mi], &bf[nj >> 1][(nj & 1) * 2]);
        }
    }

    // ---- epilogue: C fragment layout m16n8 ----
    const int crow = m0 + wm * 32 + (lane >> 2);
    const int ccol = n0 + wn * 64 + (lane & 3) * 2;
    #pragma unroll
    for (int mi = 0; mi < 2; mi++) {
        #pragma unroll
        for (int nj = 0; nj < 8; nj++) {
            float* p0 = C + (size_t)(crow + mi * 16) * DIMD + ccol + nj * 8;
            float* p1 = C + (size_t)(crow + mi * 16 + 8) * DIMD + ccol + nj * 8;
            *(float2*)p0 = make_float2(acc[mi][nj][0], acc[mi][nj][1]);
            *(float2*)p1 = make_float2(acc[mi][nj][2], acc[mi][nj][3]);
        }
    }
}

// ---------------------------------------------------------------------------
// RMSNorm (per head) + gathered 2D RoPE for q and k, in place.
// ---------------------------------------------------------------------------
__global__ __launch_bounds__(128)
void normrope(float* __restrict__ q, float* __restrict__ k,
              const float* __restrict__ qg, const float* __restrict__ kg,
              const float* __restrict__ cosT, const float* __restrict__ sinT,
              const int* __restrict__ ridx)
{
    const int token = blockIdx.x;            // b*N + n
    const int n = token & (NTOK - 1);
    const int lane = threadIdx.x & 31;
    const int w = threadIdx.x >> 5;

    const int rid = ridx[n];
    const bool dorope = (rid >= 0);
    float c0 = 1.f, c1 = 1.f, s0 = 0.f, s1 = 0.f;
    if (dorope) {
        c0 = cosT[rid * HD + lane];
        c1 = cosT[rid * HD + lane + 32];
        s0 = sinT[rid * HD + lane];
        s1 = sinT[rid * HD + lane + 32];
    }
    const float qg0 = qg[lane], qg1 = qg[lane + 32];
    const float kg0 = kg[lane], kg1 = kg[lane + 32];

    #pragma unroll
    for (int hh = 0; hh < 4; hh++) {
        const int h = w * 4 + hh;
        const size_t base = (size_t)token * DIMD + h * HD;

        {
            float x0 = q[base + lane];
            float x1 = q[base + lane + 32];
            float ss = x0 * x0 + x1 * x1;
            #pragma unroll
            for (int off = 16; off >= 1; off >>= 1)
                ss += __shfl_xor_sync(0xffffffffu, ss, off);
            float r = rsqrtf(ss * (1.f / 64.f) + 1e-6f);
            float y0 = x0 * r * qg0;
            float y1 = x1 * r * qg1;
            q[base + lane]      = dorope ? (y0 * c0 - y1 * s0) : y0;
            q[base + lane + 32] = dorope ? (y1 * c1 + y0 * s1) : y1;
        }
        {
            float x0 = k[base + lane];
            float x1 = k[base + lane + 32];
            float ss = x0 * x0 + x1 * x1;
            #pragma unroll
            for (int off = 16; off >= 1; off >>= 1)
                ss += __shfl_xor_sync(0xffffffffu, ss, off);
            float r = rsqrtf(ss * (1.f / 64.f) + 1e-6f);
            float y0 = x0 * r * kg0;
            float y1 = x1 * r * kg1;
            k[base + lane]      = dorope ? (y0 * c0 - y1 * s0) : y0;
            k[base + lane + 32] = dorope ? (y1 * c1 + y0 * s1) : y1;
        }
    }
}

// ---------------------------------------------------------------------------
// Attention: per (b, h, 128-query tile). 16 key tiles of 64.
// Soft cap bounds scores to (-50,50): exp without running max is fp32-safe.
// ---------------------------------------------------------------------------
#define QT_STRIDE 132
#define KV_STRIDE 68
#define SM_QT 0
#define SM_KT (64 * QT_STRIDE)
#define SM_VS (SM_KT + 64 * KV_STRIDE)
#define SM_PT (SM_VS + 64 * KV_STRIDE)
#define SM_RS (SM_PT + 64 * QT_STRIDE)
#define ATT_SMEM_FLOATS (SM_RS + 128)
#define ATT_SMEM_BYTES (ATT_SMEM_FLOATS * 4)

__global__ __launch_bounds__(256)
void attn_kernel(const float* __restrict__ q, const float* __restrict__ k,
                 const float* __restrict__ v,
                 const unsigned char* __restrict__ mask,
                 float* __restrict__ ctx)
{
    extern __shared__ float sm[];
    float (*Qt)[QT_STRIDE] = (float(*)[QT_STRIDE])(sm + SM_QT);
    float (*Kt)[KV_STRIDE] = (float(*)[KV_STRIDE])(sm + SM_KT);
    float (*Vs)[KV_STRIDE] = (float(*)[KV_STRIDE])(sm + SM_VS);
    float (*Pt)[QT_STRIDE] = (float(*)[QT_STRIDE])(sm + SM_PT);
    float* rowsum = sm + SM_RS;

    const int tid = threadIdx.x;
    const int tx = tid & 15;
    const int ty = tid >> 4;
    const int m0 = blockIdx.x * 128;
    const int h = blockIdx.y;
    const int b = blockIdx.z;
    const int mmode = g_maskmode;        // uniform across grid

    const size_t head_off = (size_t)h * HD;
    const size_t brow = (size_t)b * NTOK;

    #pragma unroll
    for (int u = 0; u < 8; u++) {
        int f = tid + 256 * u;
        int row = f >> 4;
        int c4 = (f & 15) * 4;
        float4 val = *(const float4*)(q + (brow + m0 + row) * DIMD + head_off + c4);
        Qt[c4 + 0][row] = val.x; Qt[c4 + 1][row] = val.y;
        Qt[c4 + 2][row] = val.z; Qt[c4 + 3][row] = val.w;
    }
    if (tid < 128) rowsum[tid] = 0.f;

    float acc[8][4];
    #pragma unroll
    for (int i = 0; i < 8; i++)
        #pragma unroll
        for (int j = 0; j < 4; j++) acc[i][j] = 0.f;

    for (int k0 = 0; k0 < NTOK; k0 += 64) {
        __syncthreads();
        #pragma unroll
        for (int u = 0; u < 4; u++) {
            int f = tid + 256 * u;
            int row = f >> 4;
            int c4 = (f & 15) * 4;
            float4 kv = *(const float4*)(k + (brow + k0 + row) * DIMD + head_off + c4);
            Kt[c4 + 0][row] = kv.x; Kt[c4 + 1][row] = kv.y;
            Kt[c4 + 2][row] = kv.z; Kt[c4 + 3][row] = kv.w;
            float4 vv = *(const float4*)(v + (brow + k0 + row) * DIMD + head_off + c4);
            *(float4*)&Vs[row][c4] = vv;
        }
        __syncthreads();

        // ---- phase A: S = Q K^T ----
        float s[8][4];
        #pragma unroll
        for (int i = 0; i < 8; i++)
            #pragma unroll
            for (int j = 0; j < 4; j++) s[i][j] = 0.f;

        #pragma unroll 4
        for (int kk = 0; kk < 64; kk++) {
            float4 a0 = *(const float4*)&Qt[kk][ty * 8];
            float4 a1 = *(const float4*)&Qt[kk][ty * 8 + 4];
            float4 b0 = *(const float4*)&Kt[kk][tx * 4];
            float a[8] = {a0.x, a0.y, a0.z, a0.w, a1.x, a1.y, a1.z, a1.w};
            float bb[4] = {b0.x, b0.y, b0.z, b0.w};
            #pragma unroll
            for (int i = 0; i < 8; i++)
                #pragma unroll
                for (int j = 0; j < 4; j++) s[i][j] += a[i] * bb[j];
        }

        // ---- soft cap + mask + exp ----
        float rs[8];
        #pragma unroll
        for (int i = 0; i < 8; i++) {
            const int qrow = m0 + ty * 8 + i;
            int mm[4];
            if (mmode == 1) {
                uchar4 mk = *(const uchar4*)(mask + (size_t)qrow * NTOK + k0 + tx * 4);
                mm[0] = mk.x; mm[1] = mk.y; mm[2] = mk.z; mm[3] = mk.w;
            } else {
                const int* m32 = (const int*)mask;
                int4 mk = *(const int4*)(m32 + (size_t)qrow * NTOK + k0 + tx * 4);
                mm[0] = mk.x; mm[1] = mk.y; mm[2] = mk.z; mm[3] = mk.w;
            }
            rs[i] = 0.f;
            #pragma unroll
            for (int j = 0; j < 4; j++) {
                float sc = s[i][j] * ATT_SCALE;
                sc = SOFT_CAP * tanhf(sc * (1.f / SOFT_CAP));
                float p = mm[j] ? __expf(sc) : 0.f;
                s[i][j] = p;
                rs[i] += p;
            }
        }
        #pragma unroll
        for (int i = 0; i < 8; i++) {
            rs[i] += __shfl_xor_sync(0xffffffffu, rs[i], 8);
            rs[i] += __shfl_xor_sync(0xffffffffu, rs[i], 4);
            rs[i] += __shfl_xor_sync(0xffffffffu, rs[i], 2);
            rs[i] += __shfl_xor_sync(0xffffffffu, rs[i], 1);
        }
        if (tx == 0) {
            #pragma unroll
            for (int i = 0; i < 8; i++) rowsum[ty * 8 + i] += rs[i];
        }

        #pragma unroll
        for (int j = 0; j < 4; j++) {
            *(float4*)&Pt[tx * 4 + j][ty * 8] =
                make_float4(s[0][j], s[1][j], s[2][j], s[3][j]);
            *(float4*)&Pt[tx * 4 + j][ty * 8 + 4] =
                make_float4(s[4][j], s[5][j], s[6][j], s[7][j]);
        }
        __syncthreads();

        // ---- phase B: acc += P V ----
        #pragma unroll 4
        for (int kk = 0; kk < 64; kk++) {
            float4 a0 = *(const float4*)&Pt[kk][ty * 8];
            float4 a1 = *(const float4*)&Pt[kk][ty * 8 + 4];
            float4 b0 = *(const float4*)&Vs[kk][tx * 4];
            float a[8] = {a0.x, a0.y, a0.z, a0.w, a1.x, a1.y, a1.z, a1.w};
            float bb[4] = {b0.x, b0.y, b0.z, b0.w};
            #pragma unroll
            for (int i = 0; i < 8; i++)
                #pragma unroll
                for (int j = 0; j < 4; j++) acc[i][j] += a[i] * bb[j];
        }
    }
    __syncthreads();

    #pragma unroll
    for (int i = 0; i < 8; i++) {
        float inv = 1.f / rowsum[ty * 8 + i];
        float4 o = make_float4(acc[i][0] * inv, acc[i][1] * inv,
                               acc[i][2] * inv, acc[i][3] * inv);
        *(float4*)(ctx + (brow + m0 + ty * 8 + i) * DIMD + head_off + tx * 4) = o;
    }
}

// ---------------------------------------------------------------------------
extern "C" void kernel_launch(void* const* d_in, const int* in_sizes, int n_in,
                              void* d_out, int out_size)
{
    (void)in_sizes; (void)n_in; (void)out_size;
    const float* x   = (const float*)d_in[0];
    const float* Wq  = (const float*)d_in[1];
    const float* Wk  = (const float*)d_in[2];
    const float* Wv  = (const float*)d_in[3];
    const float* Wo  = (const float*)d_in[4];
    const float* qg  = (const float*)d_in[5];
    const float* kg  = (const float*)d_in[6];
    const float* cosT = (const float*)d_in[7];
    const float* sinT = (const float*)d_in[8];
    const int*   ridx = (const int*)d_in[9];
    const unsigned char* mask = (const unsigned char*)d_in[10];
    float* out = (float*)d_out;

    float *qp, *kp, *vp, *cp;
    cudaGetSymbolAddress((void**)&qp, g_q);
    cudaGetSymbolAddress((void**)&kp, g_k);
    cudaGetSymbolAddress((void**)&vp, g_v);
    cudaGetSymbolAddress((void**)&cp, g_ctx);

    cudaFuncSetAttribute(attn_kernel,
                         cudaFuncAttributeMaxDynamicSharedMemorySize,
                         ATT_SMEM_BYTES);

    detect_maskmode<<<1, 1>>>(mask);

    dim3 gemm_grid(DIMD / 128, MTOT / 128);   // (8, 64)
    tc_gemm_nt<<<gemm_grid, 256>>>(x, Wq, qp);
    tc_gemm_nt<<<gemm_grid, 256>>>(x, Wk, kp);
    tc_gemm_nt<<<gemm_grid, 256>>>(x, Wv, vp);

    normrope<<<MTOT, 128>>>(qp, kp, qg, kg, cosT, sinT, ridx);

    dim3 att_grid(NTOK / 128, NH, BSZ);       // (8, 16, 8)
    attn_kernel<<<att_grid, 256, ATT_SMEM_BYTES>>>(qp, kp, vp, mask, cp);

    tc_gemm_nt<<<gemm_grid, 256>>>(cp, Wo, out);
}

// round 6
// speedup vs baseline: 2.1382x; 1.3759x over previous
#include <cuda_runtime.h>
#include <cuda_bf16.h>
#include <math.h>
#include <stdint.h>

#define DIMD 1024
#define NTOK 1024
#define BSZ 8
#define NH 16
#define HD 64
#define MTOT (BSZ * NTOK)   // 8192
#define ATT_SCALE 0.125f    // 64^-0.5
#define SOFT_CAP 50.0f

// ---------------- scratch (device globals; no allocation allowed) ----------
__device__ float g_q[MTOT * DIMD];
__device__ float g_k[MTOT * DIMD];
__device__ float g_v[MTOT * DIMD];
__device__ float g_ctx[MTOT * DIMD];
__device__ __nv_bfloat16 g_qh[MTOT * DIMD];
__device__ __nv_bfloat16 g_ql[MTOT * DIMD];
__device__ __nv_bfloat16 g_kh[MTOT * DIMD];
__device__ __nv_bfloat16 g_kl[MTOT * DIMD];
__device__ __nv_bfloat16 g_vh[MTOT * DIMD];
__device__ __nv_bfloat16 g_vl[MTOT * DIMD];
__device__ uint32_t g_maskbits[NTOK * 32];
__device__ int g_maskmode;   // 1 = uint8 layout, 4 = int32/float32 word layout

// ---------------------------------------------------------------------------
__global__ void detect_maskmode(const unsigned char* __restrict__ m)
{
    bool u8ok = true;
    for (int i = 0; i < 64; i++)
        if (m[(size_t)i * 1025] == 0) { u8ok = false; break; }
    g_maskmode = u8ok ? 1 : 4;
}

// Build bitmask: g_maskbits[row][w] bit b = mask[row][w*32+b] != 0
__global__ __launch_bounds__(256)
void build_maskbits(const unsigned char* __restrict__ m)
{
    int t = blockIdx.x * 256 + threadIdx.x;   // 0..32767
    int row = t >> 5, word = t & 31;
    uint32_t bits = 0;
    if (g_maskmode == 1) {
        const uint32_t* p = (const uint32_t*)(m + (size_t)row * NTOK + word * 32);
        #pragma unroll
        for (int i = 0; i < 8; i++) {
            uint32_t v = p[i];
            #pragma unroll
            for (int bq = 0; bq < 4; bq++)
                if ((v >> (8 * bq)) & 0xffu) bits |= 1u << (i * 4 + bq);
        }
    } else {
        const int4* p = (const int4*)((const int*)m + (size_t)row * NTOK + word * 32);
        #pragma unroll
        for (int i = 0; i < 8; i++) {
            int4 v = p[i];
            if (v.x) bits |= 1u << (i * 4 + 0);
            if (v.y) bits |= 1u << (i * 4 + 1);
            if (v.z) bits |= 1u << (i * 4 + 2);
            if (v.w) bits |= 1u << (i * 4 + 3);
        }
    }
    g_maskbits[row * 32 + word] = bits;
}

// ---------------------------------------------------------------------------
// MMA / ldmatrix helpers
// ---------------------------------------------------------------------------
__device__ __forceinline__ void ldsm_x4(uint32_t* r, uint32_t addr)
{
    asm volatile("ldmatrix.sync.aligned.m8n8.x4.shared.b16 {%0,%1,%2,%3}, [%4];\n"
                 : "=r"(r[0]), "=r"(r[1]), "=r"(r[2]), "=r"(r[3]) : "r"(addr));
}
__device__ __forceinline__ void ldsm_x4_t(uint32_t* r, uint32_t addr)
{
    asm volatile("ldmatrix.sync.aligned.m8n8.x4.trans.shared.b16 {%0,%1,%2,%3}, [%4];\n"
                 : "=r"(r[0]), "=r"(r[1]), "=r"(r[2]), "=r"(r[3]) : "r"(addr));
}
__device__ __forceinline__ void mma16816(float* c, const uint32_t* a, const uint32_t* b)
{
    asm volatile("mma.sync.aligned.m16n8k16.row.col.f32.bf16.bf16.f32 "
                 "{%0,%1,%2,%3}, {%4,%5,%6,%7}, {%8,%9}, {%0,%1,%2,%3};\n"
                 : "+f"(c[0]), "+f"(c[1]), "+f"(c[2]), "+f"(c[3])
                 : "r"(a[0]), "r"(a[1]), "r"(a[2]), "r"(a[3]),
                   "r"(b[0]), "r"(b[1]));
}
__device__ __forceinline__ uint32_t pack_bf2(__nv_bfloat16 a, __nv_bfloat16 b)
{
    __nv_bfloat162 t(a, b);
    return *reinterpret_cast<uint32_t*>(&t);
}
// split two floats into bf16x2 hi and bf16x2 lo words
__device__ __forceinline__ void psplit(float x, float y, uint32_t& hi, uint32_t& lo)
{
    __nv_bfloat16 hx = __float2bfloat16(x), hy = __float2bfloat16(y);
    __nv_bfloat16 lx = __float2bfloat16(x - __bfloat162float(hx));
    __nv_bfloat16 ly = __float2bfloat16(y - __bfloat162float(hy));
    hi = pack_bf2(hx, hy); lo = pack_bf2(lx, ly);
}

// ---------------------------------------------------------------------------
// Tensor-core GEMM (split-bf16): C[M,1024] = A @ B^T (NT) — unchanged (proven)
// ---------------------------------------------------------------------------
#define TCS 40

__device__ __forceinline__ void split_store(__nv_bfloat16* hi_base, __nv_bfloat16* lo_base,
                                            int off, float4 v)
{
    __nv_bfloat16 h0 = __float2bfloat16(v.x);
    __nv_bfloat16 h1 = __float2bfloat16(v.y);
    __nv_bfloat16 h2 = __float2bfloat16(v.z);
    __nv_bfloat16 h3 = __float2bfloat16(v.w);
    __nv_bfloat16 l0 = __float2bfloat16(v.x - __bfloat162float(h0));
    __nv_bfloat16 l1 = __float2bfloat16(v.y - __bfloat162float(h1));
    __nv_bfloat16 l2 = __float2bfloat16(v.z - __bfloat162float(h2));
    __nv_bfloat16 l3 = __float2bfloat16(v.w - __bfloat162float(h3));
    *(__nv_bfloat162*)(hi_base + off)     = __nv_bfloat162(h0, h1);
    *(__nv_bfloat162*)(hi_base + off + 2) = __nv_bfloat162(h2, h3);
    *(__nv_bfloat162*)(lo_base + off)     = __nv_bfloat162(l0, l1);
    *(__nv_bfloat162*)(lo_base + off + 2) = __nv_bfloat162(l2, l3);
}

__global__ __launch_bounds__(256)
void tc_gemm_nt(const float* __restrict__ A, const float* __restrict__ B,
                float* __restrict__ C)
{
    __shared__ __align__(16) __nv_bfloat16 Ah[128 * TCS];
    __shared__ __align__(16) __nv_bfloat16 Al[128 * TCS];
    __shared__ __align__(16) __nv_bfloat16 Bh[128 * TCS];
    __shared__ __align__(16) __nv_bfloat16 Bl[128 * TCS];

    const int tid = threadIdx.x;
    const int lane = tid & 31;
    const int wid = tid >> 5;
    const int wm = wid & 3;
    const int wn = wid >> 2;
    const int m0 = blockIdx.y * 128;
    const int n0 = blockIdx.x * 128;

    int lrow[4], lc4[4], soff[4];
    #pragma unroll
    for (int u = 0; u < 4; u++) {
        int f = tid + 256 * u;
        lrow[u] = f >> 3;
        lc4[u]  = (f & 7) * 4;
        soff[u] = lrow[u] * TCS + lc4[u];
    }

    const uint32_t Ah_b = (uint32_t)__cvta_generic_to_shared(Ah);
    const uint32_t Al_b = (uint32_t)__cvta_generic_to_shared(Al);
    const uint32_t Bh_b = (uint32_t)__cvta_generic_to_shared(Bh);
    const uint32_t Bl_b = (uint32_t)__cvta_generic_to_shared(Bl);

    const int a_row = wm * 32 + (lane & 15);
    const int a_kad = (lane & 16) ? 8 : 0;
    const uint32_t a_off0 = (uint32_t)(a_row * TCS + a_kad) * 2;
    const int b_row = wn * 64 + (lane & 7) + ((lane & 16) ? 8 : 0);
    const int b_kad = (lane & 8) ? 8 : 0;
    const uint32_t b_off0 = (uint32_t)(b_row * TCS + b_kad) * 2;

    float acc[2][8][4];
    #pragma unroll
    for (int mi = 0; mi < 2; mi++)
        #pragma unroll
        for (int nj = 0; nj < 8; nj++)
            #pragma unroll
            for (int c = 0; c < 4; c++) acc[mi][nj][c] = 0.f;

    float4 av[4], bv[4];
    #pragma unroll
    for (int u = 0; u < 4; u++) {
        av[u] = *(const float4*)(A + (size_t)(m0 + lrow[u]) * DIMD + lc4[u]);
        bv[u] = *(const float4*)(B + (size_t)(n0 + lrow[u]) * DIMD + lc4[u]);
    }

    for (int k0 = 0; k0 < DIMD; k0 += 32) {
        __syncthreads();
        #pragma unroll
        for (int u = 0; u < 4; u++) {
            split_store(Ah, Al, soff[u], av[u]);
            split_store(Bh, Bl, soff[u], bv[u]);
        }
        __syncthreads();

        if (k0 + 32 < DIMD) {
            #pragma unroll
            for (int u = 0; u < 4; u++) {
                av[u] = *(const float4*)(A + (size_t)(m0 + lrow[u]) * DIMD + k0 + 32 + lc4[u]);
                bv[u] = *(const float4*)(B + (size_t)(n0 + lrow[u]) * DIMD + k0 + 32 + lc4[u]);
            }
        }

        #pragma unroll
        for (int kk = 0; kk < 32; kk += 16) {
            const uint32_t akk = a_off0 + kk * 2;
            const uint32_t bkk = b_off0 + kk * 2;

            uint32_t ah[2][4], al[2][4], bf[4][4];
            ldsm_x4(ah[0], Ah_b + akk);
            ldsm_x4(ah[1], Ah_b + akk + 16 * TCS * 2);
            ldsm_x4(al[0], Al_b + akk);
            ldsm_x4(al[1], Al_b + akk + 16 * TCS * 2);
            #pragma unroll
            for (int nq = 0; nq < 4; nq++)
                ldsm_x4(bf[nq], Bh_b + bkk + nq * 16 * TCS * 2);

            #pragma unroll
            for (int mi = 0; mi < 2; mi++)
                #pragma unroll
                for (int nj = 0; nj < 8; nj++)
                    mma16816(acc[mi][nj], ah[mi], &bf[nj >> 1][(nj & 1) * 2]);
            #pragma unroll
            for (int mi = 0; mi < 2; mi++)
                #pragma unroll
                for (int nj = 0; nj < 8; nj++)
                    mma16816(acc[mi][nj], al[mi], &bf[nj >> 1][(nj & 1) * 2]);

            #pragma unroll
            for (int nq = 0; nq < 4; nq++)
                ldsm_x4(bf[nq], Bl_b + bkk + nq * 16 * TCS * 2);
            #pragma unroll
            for (int mi = 0; mi < 2; mi++)
                #pragma unroll
                for (int nj = 0; nj < 8; nj++)
                    mma16816(acc[mi][nj], ah[mi], &bf[nj >> 1][(nj & 1) * 2]);
        }
    }

    const int crow = m0 + wm * 32 + (lane >> 2);
    const int ccol = n0 + wn * 64 + (lane & 3) * 2;
    #pragma unroll
    for (int mi = 0; mi < 2; mi++) {
        #pragma unroll
        for (int nj = 0; nj < 8; nj++) {
            float* p0 = C + (size_t)(crow + mi * 16) * DIMD + ccol + nj * 8;
            float* p1 = C + (size_t)(crow + mi * 16 + 8) * DIMD + ccol + nj * 8;
            *(float2*)p0 = make_float2(acc[mi][nj][0], acc[mi][nj][1]);
            *(float2*)p1 = make_float2(acc[mi][nj][2], acc[mi][nj][3]);
        }
    }
}

// ---------------------------------------------------------------------------
// RMSNorm + RoPE -> split-bf16 q/k; also split v. (fp32 in, bf16 hi/lo out)
// ---------------------------------------------------------------------------
__global__ __launch_bounds__(128)
void normrope(const float* __restrict__ q, const float* __restrict__ k,
              const float* __restrict__ v,
              const float* __restrict__ qg, const float* __restrict__ kg,
              const float* __restrict__ cosT, const float* __restrict__ sinT,
              const int* __restrict__ ridx,
              __nv_bfloat16* __restrict__ qh, __nv_bfloat16* __restrict__ ql,
              __nv_bfloat16* __restrict__ kh, __nv_bfloat16* __restrict__ kl,
              __nv_bfloat16* __restrict__ vh, __nv_bfloat16* __restrict__ vl)
{
    const int token = blockIdx.x;
    const int n = token & (NTOK - 1);
    const int lane = threadIdx.x & 31;
    const int w = threadIdx.x >> 5;

    const int rid = ridx[n];
    const bool dorope = (rid >= 0);
    float c0 = 1.f, c1 = 1.f, s0 = 0.f, s1 = 0.f;
    if (dorope) {
        c0 = cosT[rid * HD + lane];
        c1 = cosT[rid * HD + lane + 32];
        s0 = sinT[rid * HD + lane];
        s1 = sinT[rid * HD + lane + 32];
    }
    const float qg0 = qg[lane], qg1 = qg[lane + 32];
    const float kg0 = kg[lane], kg1 = kg[lane + 32];

    #pragma unroll
    for (int hh = 0; hh < 4; hh++) {
        const int h = w * 4 + hh;
        const size_t base = (size_t)token * DIMD + h * HD;

        {
            float x0 = q[base + lane];
            float x1 = q[base + lane + 32];
            float ss = x0 * x0 + x1 * x1;
            #pragma unroll
            for (int off = 16; off >= 1; off >>= 1)
                ss += __shfl_xor_sync(0xffffffffu, ss, off);
            float r = rsqrtf(ss * (1.f / 64.f) + 1e-6f);
            float y0 = x0 * r * qg0;
            float y1 = x1 * r * qg1;
            float o0 = dorope ? (y0 * c0 - y1 * s0) : y0;
            float o1 = dorope ? (y1 * c1 + y0 * s1) : y1;
            __nv_bfloat16 h0 = __float2bfloat16(o0);
            __nv_bfloat16 h1 = __float2bfloat16(o1);
            qh[base + lane]      = h0;
            qh[base + lane + 32] = h1;
            ql[base + lane]      = __float2bfloat16(o0 - __bfloat162float(h0));
            ql[base + lane + 32] = __float2bfloat16(o1 - __bfloat162float(h1));
        }
        {
            float x0 = k[base + lane];
            float x1 = k[base + lane + 32];
            float ss = x0 * x0 + x1 * x1;
            #pragma unroll
            for (int off = 16; off >= 1; off >>= 1)
                ss += __shfl_xor_sync(0xffffffffu, ss, off);
            float r = rsqrtf(ss * (1.f / 64.f) + 1e-6f);
            float y0 = x0 * r * kg0;
            float y1 = x1 * r * kg1;
            float o0 = dorope ? (y0 * c0 - y1 * s0) : y0;
            float o1 = dorope ? (y1 * c1 + y0 * s1) : y1;
            __nv_bfloat16 h0 = __float2bfloat16(o0);
            __nv_bfloat16 h1 = __float2bfloat16(o1);
            kh[base + lane]      = h0;
            kh[base + lane + 32] = h1;
            kl[base + lane]      = __float2bfloat16(o0 - __bfloat162float(h0));
            kl[base + lane + 32] = __float2bfloat16(o1 - __bfloat162float(h1));
        }
    }

    // split V: 1024 floats / 128 threads = 8 each
    {
        const size_t vbase = (size_t)token * DIMD + threadIdx.x * 8;
        float4 a = *(const float4*)(v + vbase);
        float4 b2 = *(const float4*)(v + vbase + 4);
        split_store(vh, vl, 0, a);      // careful: split_store indexes from base ptr
        // split_store writes hi_base[off..], so call with offset pointers:
        // (we inline instead)
        (void)a; (void)b2;
        // inline split for clarity/correctness:
        const float vals[8] = {a.x, a.y, a.z, a.w, b2.x, b2.y, b2.z, b2.w};
        #pragma unroll
        for (int i = 0; i < 8; i += 2) {
            __nv_bfloat16 h0 = __float2bfloat16(vals[i]);
            __nv_bfloat16 h1 = __float2bfloat16(vals[i + 1]);
            *(__nv_bfloat162*)(vh + vbase + i) = __nv_bfloat162(h0, h1);
            *(__nv_bfloat162*)(vl + vbase + i) =
                __nv_bfloat162(__float2bfloat16(vals[i]     - __bfloat162float(h0)),
                               __float2bfloat16(vals[i + 1] - __bfloat162float(h1)));
        }
    }
}

// ---------------------------------------------------------------------------
// Tensor-core attention: block = (128 q) x (b,h); 8 warps, each m16 x n64.
// S = QhKh + QlKh + QhKl; softcap+mask+exp in regs; P split hi/lo repacked
// register-to-register into A frags; PV = PhVh + PlVh + PhVl via ldsm.trans V.
// No running max needed (|s| <= 50 after cap).
// ---------------------------------------------------------------------------
#define AKS 72   // smem row stride (bf16) for 64-wide tiles

__global__ __launch_bounds__(256)
void attn_tc(const __nv_bfloat16* __restrict__ qh, const __nv_bfloat16* __restrict__ ql,
             const __nv_bfloat16* __restrict__ kh, const __nv_bfloat16* __restrict__ kl,
             const __nv_bfloat16* __restrict__ vh, const __nv_bfloat16* __restrict__ vl,
             const uint32_t* __restrict__ mbits,
             float* __restrict__ ctx)
{
    __shared__ __align__(16) __nv_bfloat16 sKh[64 * AKS];
    __shared__ __align__(16) __nv_bfloat16 sKl[64 * AKS];
    __shared__ __align__(16) __nv_bfloat16 sVh[64 * AKS];
    __shared__ __align__(16) __nv_bfloat16 sVl[64 * AKS];

    const int tid = threadIdx.x;
    const int lane = tid & 31;
    const int w = tid >> 5;
    const int m0 = blockIdx.x * 128;
    const int h = blockIdx.y;
    const int b = blockIdx.z;
    const int head_off = h * HD;
    const int brow = b * NTOK;

    const uint32_t sKh_b = (uint32_t)__cvta_generic_to_shared(sKh);
    const uint32_t sKl_b = (uint32_t)__cvta_generic_to_shared(sKl);
    const uint32_t sVh_b = (uint32_t)__cvta_generic_to_shared(sVh);
    const uint32_t sVl_b = (uint32_t)__cvta_generic_to_shared(sVl);

    // ---- Q fragments (held for whole kernel) ----
    const int mrow0 = m0 + w * 16 + (lane >> 2);       // query row within batch
    const size_t qg0 = (size_t)(brow + mrow0) * DIMD + head_off + (lane & 3) * 2;
    uint32_t qhf[4][4], qlf[4][4];
    #pragma unroll
    for (int c = 0; c < 4; c++) {
        qhf[c][0] = *(const uint32_t*)(qh + qg0 + 16 * c);
        qhf[c][1] = *(const uint32_t*)(qh + qg0 + 8 * DIMD + 16 * c);
        qhf[c][2] = *(const uint32_t*)(qh + qg0 + 16 * c + 8);
        qhf[c][3] = *(const uint32_t*)(qh + qg0 + 8 * DIMD + 16 * c + 8);
        qlf[c][0] = *(const uint32_t*)(ql + qg0 + 16 * c);
        qlf[c][1] = *(const uint32_t*)(ql + qg0 + 8 * DIMD + 16 * c);
        qlf[c][2] = *(const uint32_t*)(ql + qg0 + 16 * c + 8);
        qlf[c][3] = *(const uint32_t*)(ql + qg0 + 8 * DIMD + 16 * c + 8);
    }

    // ldsm address lane-components
    const int k_r = (lane & 7) + ((lane & 16) ? 8 : 0);   // K non-trans: row within 16-n group
    const int k_c = (lane & 8) ? 8 : 0;                   // K: k-col add
    const int v_r = (lane & 7) + ((lane & 8) ? 8 : 0);    // V trans: key-row add within chunk
    const int v_c = (lane & 16) ? 8 : 0;                  // V: n-col add

    float acc[8][4];
    #pragma unroll
    for (int j = 0; j < 8; j++)
        #pragma unroll
        for (int c = 0; c < 4; c++) acc[j][c] = 0.f;
    float rs0 = 0.f, rs1 = 0.f;

    const int mrow1 = mrow0 + 8;

    for (int k0 = 0; k0 < NTOK; k0 += 64) {
        __syncthreads();
        // ---- load K/V tiles (hi/lo) into smem ----
        #pragma unroll
        for (int it = 0; it < 2; it++) {
            int slot = tid + 256 * it;
            int row = slot >> 3;
            int seg = (slot & 7) * 8;
            size_t src = (size_t)(brow + k0 + row) * DIMD + head_off + seg;
            int dst = row * AKS + seg;
            *(uint4*)(sKh + dst) = *(const uint4*)(kh + src);
            *(uint4*)(sKl + dst) = *(const uint4*)(kl + src);
            *(uint4*)(sVh + dst) = *(const uint4*)(vh + src);
            *(uint4*)(sVl + dst) = *(const uint4*)(vl + src);
        }
        __syncthreads();

        // ---- S = Q K^T over hd (4 k16 chunks) ----
        float sf[8][4];
        #pragma unroll
        for (int j = 0; j < 8; j++)
            #pragma unroll
            for (int c = 0; c < 4; c++) sf[j][c] = 0.f;

        #pragma unroll
        for (int c = 0; c < 4; c++) {
            uint32_t kf[4][4];
            #pragma unroll
            for (int q = 0; q < 4; q++)
                ldsm_x4(kf[q], sKh_b + (uint32_t)((q * 16 + k_r) * AKS + c * 16 + k_c) * 2);
            #pragma unroll
            for (int j = 0; j < 8; j++)
                mma16816(sf[j], qhf[c], &kf[j >> 1][(j & 1) * 2]);
            #pragma unroll
            for (int j = 0; j < 8; j++)
                mma16816(sf[j], qlf[c], &kf[j >> 1][(j & 1) * 2]);
            #pragma unroll
            for (int q = 0; q < 4; q++)
                ldsm_x4(kf[q], sKl_b + (uint32_t)((q * 16 + k_r) * AKS + c * 16 + k_c) * 2);
            #pragma unroll
            for (int j = 0; j < 8; j++)
                mma16816(sf[j], qhf[c], &kf[j >> 1][(j & 1) * 2]);
        }

        // ---- soft cap + mask + exp ----
        const int wb = k0 >> 5;
        const uint32_t mw00 = mbits[mrow0 * 32 + wb];
        const uint32_t mw01 = mbits[mrow0 * 32 + wb + 1];
        const uint32_t mw10 = mbits[mrow1 * 32 + wb];
        const uint32_t mw11 = mbits[mrow1 * 32 + wb + 1];

        #pragma unroll
        for (int j = 0; j < 8; j++) {
            int idx = j * 8 + (lane & 3) * 2;       // 0..62, pair stays in one word
            uint32_t w0 = (j < 4) ? mw00 : mw01;
            uint32_t w1 = (j < 4) ? mw10 : mw11;
            int sh = idx & 31;
            #pragma unroll
            for (int e = 0; e < 2; e++) {
                uint32_t bit0 = (w0 >> (sh + e)) & 1u;
                uint32_t bit1 = (w1 >> (sh + e)) & 1u;
                float sc0 = sf[j][e] * ATT_SCALE;
                float sc1 = sf[j][2 + e] * ATT_SCALE;
                sc0 = SOFT_CAP * tanhf(sc0 * (1.f / SOFT_CAP));
                sc1 = SOFT_CAP * tanhf(sc1 * (1.f / SOFT_CAP));
                float p0 = bit0 ? __expf(sc0) : 0.f;
                float p1 = bit1 ? __expf(sc1) : 0.f;
                sf[j][e] = p0;
                sf[j][2 + e] = p1;
                rs0 += p0;
                rs1 += p1;
            }
        }

        // ---- PV: acc += P V  (P repacked in registers) ----
        #pragma unroll
        for (int c = 0; c < 4; c++) {
            uint32_t pah[4], pal[4];
            psplit(sf[2 * c][0], sf[2 * c][1], pah[0], pal[0]);
            psplit(sf[2 * c][2], sf[2 * c][3], pah[1], pal[1]);
            psplit(sf[2 * c + 1][0], sf[2 * c + 1][1], pah[2], pal[2]);
            psplit(sf[2 * c + 1][2], sf[2 * c + 1][3], pah[3], pal[3]);

            uint32_t vf[4][4];
            #pragma unroll
            for (int q = 0; q < 4; q++)
                ldsm_x4_t(vf[q], sVh_b + (uint32_t)((c * 16 + v_r) * AKS + q * 16 + v_c) * 2);
            #pragma unroll
            for (int j = 0; j < 8; j++)
                mma16816(acc[j], pah, &vf[j >> 1][(j & 1) * 2]);
            #pragma unroll
            for (int j = 0; j < 8; j++)
                mma16816(acc[j], pal, &vf[j >> 1][(j & 1) * 2]);
            #pragma unroll
            for (int q = 0; q < 4; q++)
                ldsm_x4_t(vf[q], sVl_b + (uint32_t)((c * 16 + v_r) * AKS + q * 16 + v_c) * 2);
            #pragma unroll
            for (int j = 0; j < 8; j++)
                mma16816(acc[j], pah, &vf[j >> 1][(j & 1) * 2]);
        }
    }

    // ---- normalize + store ----
    rs0 += __shfl_xor_sync(0xffffffffu, rs0, 1);
    rs0 += __shfl_xor_sync(0xffffffffu, rs0, 2);
    rs1 += __shfl_xor_sync(0xffffffffu, rs1, 1);
    rs1 += __shfl_xor_sync(0xffffffffu, rs1, 2);
    const float inv0 = 1.f / rs0;
    const float inv1 = 1.f / rs1;

    #pragma unroll
    for (int j = 0; j < 8; j++) {
        const int col = head_off + j * 8 + (lane & 3) * 2;
        *(float2*)(ctx + (size_t)(brow + mrow0) * DIMD + col) =
            make_float2(acc[j][0] * inv0, acc[j][1] * inv0);
        *(float2*)(ctx + (size_t)(brow + mrow1) * DIMD + col) =
            make_float2(acc[j][2] * inv1, acc[j][3] * inv1);
    }
}

// ---------------------------------------------------------------------------
extern "C" void kernel_launch(void* const* d_in, const int* in_sizes, int n_in,
                              void* d_out, int out_size)
{
    (void)in_sizes; (void)n_in; (void)out_size;
    const float* x   = (const float*)d_in[0];
    const float* Wq  = (const float*)d_in[1];
    const float* Wk  = (const float*)d_in[2];
    const float* Wv  = (const float*)d_in[3];
    const float* Wo  = (const float*)d_in[4];
    const float* qg  = (const float*)d_in[5];
    const float* kg  = (const float*)d_in[6];
    const float* cosT = (const float*)d_in[7];
    const float* sinT = (const float*)d_in[8];
    const int*   ridx = (const int*)d_in[9];
    const unsigned char* mask = (const unsigned char*)d_in[10];
    float* out = (float*)d_out;

    float *qp, *kp, *vp, *cp;
    __nv_bfloat16 *qhp, *qlp, *khp, *klp, *vhp, *vlp;
    uint32_t* mbp;
    cudaGetSymbolAddress((void**)&qp, g_q);
    cudaGetSymbolAddress((void**)&kp, g_k);
    cudaGetSymbolAddress((void**)&vp, g_v);
    cudaGetSymbolAddress((void**)&cp, g_ctx);
    cudaGetSymbolAddress((void**)&qhp, g_qh);
    cudaGetSymbolAddress((void**)&qlp, g_ql);
    cudaGetSymbolAddress((void**)&khp, g_kh);
    cudaGetSymbolAddress((void**)&klp, g_kl);
    cudaGetSymbolAddress((void**)&vhp, g_vh);
    cudaGetSymbolAddress((void**)&vlp, g_vl);
    cudaGetSymbolAddress((void**)&mbp, g_maskbits);

    detect_maskmode<<<1, 1>>>(mask);
    build_maskbits<<<128, 256>>>(mask);

    dim3 gemm_grid(DIMD / 128, MTOT / 128);   // (8, 64)
    tc_gemm_nt<<<gemm_grid, 256>>>(x, Wq, qp);
    tc_gemm_nt<<<gemm_grid, 256>>>(x, Wk, kp);
    tc_gemm_nt<<<gemm_grid, 256>>>(x, Wv, vp);

    normrope<<<MTOT, 128>>>(qp, kp, vp, qg, kg, cosT, sinT, ridx,
                            qhp, qlp, khp, klp, vhp, vlp);

    dim3 att_grid(NTOK / 128, NH, BSZ);       // (8, 16, 8)
    attn_tc<<<att_grid, 256>>>(qhp, qlp, khp, klp, vhp, vlp, mbp, cp);

    tc_gemm_nt<<<gemm_grid, 256>>>(cp, Wo, out);
}